// round 1
// baseline (speedup 1.0000x reference)
#include <cuda_runtime.h>
#include <stddef.h>

#define N_NODES 100000
#define N_EDGES 300000
#define NGRAPHS 3000
#define D 256
#define MSG_EPS 1e-7f
#define LN_EPS  1e-5f

// ---------------- scratch (static device allocations; no cudaMalloc) ----------------
__device__ __align__(16) float g_h  [(size_t)N_NODES * D];
__device__ __align__(16) float g_h2 [(size_t)N_NODES * D];
__device__ __align__(16) float g_agg[(size_t)N_NODES * D];
__device__ __align__(16) float g_vn [(size_t)NGRAPHS * D];
__device__ int g_off[NGRAPHS + 1];

// ---------------- node init: atom embedding sum, h_init out, h = h0 + vn_emb ----------------
__global__ void node_init_kernel(const int* __restrict__ x,
                                 const float* __restrict__ atom_emb,
                                 const float* __restrict__ vn_emb,
                                 float* __restrict__ h,
                                 float* __restrict__ agg,
                                 float* __restrict__ vn,
                                 float* __restrict__ out_hinit)
{
    int n = blockIdx.x;
    int d = threadIdx.x;
    __shared__ int xi[9];
    if (d < 9) xi[d] = x[n * 9 + d];
    __syncthreads();
    float s = 0.f;
#pragma unroll
    for (int f = 0; f < 9; f++)
        s += atom_emb[((size_t)f * 64 + xi[f]) * D + d];
    size_t idx = (size_t)n * D + d;
    out_hinit[idx] = s;
    h[idx] = s + vn_emb[d];
    agg[idx] = 0.f;
    if (n < NGRAPHS) vn[(size_t)n * D + d] = vn_emb[d];
}

// ---------------- graph segment offsets via binary search (batch is sorted) ----------------
__global__ void offsets_kernel(const int* __restrict__ batch, int* __restrict__ off)
{
    int g = blockIdx.x * blockDim.x + threadIdx.x;
    if (g > NGRAPHS) return;
    int lo = 0, hi = N_NODES;
    while (lo < hi) {
        int mid = (lo + hi) >> 1;
        if (batch[mid] < g) lo = mid + 1; else hi = mid;
    }
    off[g] = lo;
}

// ---------------- edge messages: msg = relu(h[src]+edge_emb)+eps, scatter-add to agg[dst] ----------------
__global__ void edge_msg_kernel(const float4* __restrict__ hin,
                                const int* __restrict__ ei,
                                const int* __restrict__ ea,
                                const float4* __restrict__ bond,   // [3][8][64] float4
                                float* __restrict__ agg)
{
    int e = blockIdx.x * 4 + (threadIdx.x >> 6);
    if (e >= N_EDGES) return;
    int q = threadIdx.x & 63;
    int src = __ldg(&ei[e]);
    int dst = __ldg(&ei[N_EDGES + e]);
    int a0 = __ldg(&ea[3 * e + 0]);
    int a1 = __ldg(&ea[3 * e + 1]);
    int a2 = __ldg(&ea[3 * e + 2]);
    float4 v  = hin[(size_t)src * 64 + q];
    float4 b0 = bond[(size_t)(0 * 8 + a0) * 64 + q];
    float4 b1 = bond[(size_t)(1 * 8 + a1) * 64 + q];
    float4 b2 = bond[(size_t)(2 * 8 + a2) * 64 + q];
    float mx = fmaxf(v.x + b0.x + b1.x + b2.x, 0.f) + MSG_EPS;
    float my = fmaxf(v.y + b0.y + b1.y + b2.y, 0.f) + MSG_EPS;
    float mz = fmaxf(v.z + b0.z + b1.z + b2.z, 0.f) + MSG_EPS;
    float mw = fmaxf(v.w + b0.w + b1.w + b2.w, 0.f) + MSG_EPS;
    float* base = &agg[(size_t)dst * D + q * 4];
    atomicAdd(base + 0, mx);
    atomicAdd(base + 1, my);
    atomicAdd(base + 2, mz);
    atomicAdd(base + 3, mw);
}

// ---------------- generic GEMM: out = (A1 [+A2]) @ W + bias [+ res] ----------------
// A: [M, 256] fp32 row-major. W: [256, BN] row-major. out row stride ldout.
template<int BN>
__global__ __launch_bounds__(256)
void gemm_kernel(const float* __restrict__ A1, const float* __restrict__ A2,
                 const float* __restrict__ W, const float* __restrict__ bias,
                 const float* __restrict__ res, float* __restrict__ out,
                 int M, int ldout)
{
    constexpr int BM = 64, BK = 32, K = D;
    constexpr int NG = BN / 64;
    __shared__ float As[BK][BM];
    __shared__ float Bs[BK][BN];
    const int tid = threadIdx.x;
    const int tx = tid & 15;        // 16 col-groups
    const int ty = tid >> 4;        // 16 row-groups
    const int m0 = blockIdx.x * BM;

    float acc[4][NG * 4];
#pragma unroll
    for (int i = 0; i < 4; i++)
#pragma unroll
        for (int j = 0; j < NG * 4; j++) acc[i][j] = 0.f;

    for (int k0 = 0; k0 < K; k0 += BK) {
        // --- load A tile (64 x 32), transposed into As[k][m], zero-padded past M ---
        {
            int r  = tid >> 3;            // 0..31
            int kc = (tid & 7) * 4;       // 0..28
#pragma unroll
            for (int it = 0; it < 2; it++) {
                int row = r + it * 32;
                int m = m0 + row;
                float4 v = make_float4(0.f, 0.f, 0.f, 0.f);
                if (m < M) {
                    v = *reinterpret_cast<const float4*>(&A1[(size_t)m * K + k0 + kc]);
                    if (A2) {
                        float4 w = *reinterpret_cast<const float4*>(&A2[(size_t)m * K + k0 + kc]);
                        v.x += w.x; v.y += w.y; v.z += w.z; v.w += w.w;
                    }
                }
                As[kc + 0][row] = v.x;
                As[kc + 1][row] = v.y;
                As[kc + 2][row] = v.z;
                As[kc + 3][row] = v.w;
            }
        }
        // --- load B tile (32 x BN) ---
        {
            constexpr int PASS = (BK * BN) / 1024;
            constexpr int RP   = 1024 / BN;
            int c4 = (tid % (BN / 4)) * 4;
            int rr = tid / (BN / 4);
#pragma unroll
            for (int it = 0; it < PASS; it++) {
                int kk = rr + it * RP;
                float4 v = *reinterpret_cast<const float4*>(&W[(size_t)(k0 + kk) * BN + c4]);
                *reinterpret_cast<float4*>(&Bs[kk][c4]) = v;
            }
        }
        __syncthreads();
#pragma unroll
        for (int k = 0; k < BK; k++) {
            float4 a4 = *reinterpret_cast<const float4*>(&As[k][ty * 4]);
            float av[4] = {a4.x, a4.y, a4.z, a4.w};
#pragma unroll
            for (int g = 0; g < NG; g++) {
                float4 b4 = *reinterpret_cast<const float4*>(&Bs[k][g * 64 + tx * 4]);
                float bv[4] = {b4.x, b4.y, b4.z, b4.w};
#pragma unroll
                for (int i = 0; i < 4; i++)
#pragma unroll
                    for (int j = 0; j < 4; j++)
                        acc[i][g * 4 + j] = fmaf(av[i], bv[j], acc[i][g * 4 + j]);
            }
        }
        __syncthreads();
    }
    // --- epilogue ---
#pragma unroll
    for (int i = 0; i < 4; i++) {
        int m = m0 + ty * 4 + i;
        if (m >= M) continue;
#pragma unroll
        for (int g = 0; g < NG; g++) {
            int c = g * 64 + tx * 4;
            float4 v;
            v.x = acc[i][g * 4 + 0] + bias[c + 0];
            v.y = acc[i][g * 4 + 1] + bias[c + 1];
            v.z = acc[i][g * 4 + 2] + bias[c + 2];
            v.w = acc[i][g * 4 + 3] + bias[c + 3];
            if (res) {
                float4 r4 = *reinterpret_cast<const float4*>(&res[(size_t)m * D + c]);
                v.x += r4.x; v.y += r4.y; v.z += r4.z; v.w += r4.w;
            }
            *reinterpret_cast<float4*>(&out[(size_t)m * ldout + c]) = v;
        }
    }
}

// ---------------- LayerNorm + ReLU per node (also zeroes agg for next conv) ----------------
__global__ void ln_relu_kernel(const float* __restrict__ h,
                               const float* __restrict__ gam,
                               const float* __restrict__ bet,
                               float* __restrict__ h2,
                               float* __restrict__ agg)
{
    int n = blockIdx.x, d = threadIdx.x;
    size_t idx = (size_t)n * D + d;
    float v = h[idx];
    float a = v, b = v * v;
    __shared__ float sa[8], sb[8];
    int lane = d & 31, w = d >> 5;
#pragma unroll
    for (int o = 16; o; o >>= 1) {
        a += __shfl_down_sync(0xffffffffu, a, o);
        b += __shfl_down_sync(0xffffffffu, b, o);
    }
    if (lane == 0) { sa[w] = a; sb[w] = b; }
    __syncthreads();
    if (w == 0) {
        a = (lane < 8) ? sa[lane] : 0.f;
        b = (lane < 8) ? sb[lane] : 0.f;
#pragma unroll
        for (int o = 4; o; o >>= 1) {
            a += __shfl_down_sync(0xffffffffu, a, o);
            b += __shfl_down_sync(0xffffffffu, b, o);
        }
        if (lane == 0) { sa[0] = a; sb[0] = b; }
    }
    __syncthreads();
    float mu  = sa[0] * (1.f / D);
    float var = sb[0] * (1.f / D) - mu * mu;
    float y = (v - mu) * rsqrtf(var + LN_EPS) * gam[d] + bet[d];
    h2[idx]  = fmaxf(y, 0.f);
    agg[idx] = 0.f;
}

// ---------------- virtual-node path: vn = MLP(segment_sum(h2) + vn), 8 graphs/block ----------------
__device__ __forceinline__ void ln_rows8(float (*t)[D], float (*s)[D],
                                         const float* __restrict__ gam,
                                         const float* __restrict__ bet,
                                         float* smu, float* srs)
{
    int lane = threadIdx.x & 31, w = threadIdx.x >> 5;   // warp w handles graph w
    float a = 0.f, b = 0.f;
#pragma unroll
    for (int i = 0; i < 8; i++) {
        float v = t[w][lane + 32 * i];
        a += v; b += v * v;
    }
#pragma unroll
    for (int o = 16; o; o >>= 1) {
        a += __shfl_down_sync(0xffffffffu, a, o);
        b += __shfl_down_sync(0xffffffffu, b, o);
    }
    if (lane == 0) {
        float mu = a * (1.f / D);
        float var = b * (1.f / D) - mu * mu;
        smu[w] = mu;
        srs[w] = rsqrtf(var + LN_EPS);
    }
    __syncthreads();
    int d = threadIdx.x;
    float gd = gam[d], bd = bet[d];
#pragma unroll
    for (int gg = 0; gg < 8; gg++) {
        float v = (t[gg][d] - smu[gg]) * srs[gg] * gd + bd;
        s[gg][d] = fmaxf(v, 0.f);
    }
}

__global__ void vn_mlp_kernel(const float* __restrict__ h2, const int* __restrict__ off,
                              const float* __restrict__ W1, const float* __restrict__ b1,
                              const float* __restrict__ g1, const float* __restrict__ be1,
                              const float* __restrict__ W2, const float* __restrict__ b2,
                              const float* __restrict__ g2, const float* __restrict__ be2,
                              float* __restrict__ vn)
{
    __shared__ float s[8][D];
    __shared__ float t[8][D];
    __shared__ float smu[8], srs[8];
    int d = threadIdx.x;
    int g0 = blockIdx.x * 8;

    // segment sum + current vn
#pragma unroll
    for (int gg = 0; gg < 8; gg++) {
        int g = g0 + gg;
        float acc = vn[(size_t)g * D + d];
        int n1 = off[g + 1];
        for (int n = off[g]; n < n1; n++)
            acc += h2[(size_t)n * D + d];
        s[gg][d] = acc;
    }
    __syncthreads();

    // linear 1
    float y[8];
#pragma unroll
    for (int gg = 0; gg < 8; gg++) y[gg] = b1[d];
    for (int k = 0; k < D; k++) {
        float w = W1[(size_t)k * D + d];
#pragma unroll
        for (int gg = 0; gg < 8; gg++) y[gg] = fmaf(s[gg][k], w, y[gg]);
    }
    __syncthreads();
#pragma unroll
    for (int gg = 0; gg < 8; gg++) t[gg][d] = y[gg];
    __syncthreads();
    ln_rows8(t, s, g1, be1, smu, srs);   // s = relu(LN(t))
    __syncthreads();

    // linear 2
#pragma unroll
    for (int gg = 0; gg < 8; gg++) y[gg] = b2[d];
    for (int k = 0; k < D; k++) {
        float w = W2[(size_t)k * D + d];
#pragma unroll
        for (int gg = 0; gg < 8; gg++) y[gg] = fmaf(s[gg][k], w, y[gg]);
    }
    __syncthreads();
#pragma unroll
    for (int gg = 0; gg < 8; gg++) t[gg][d] = y[gg];
    __syncthreads();
    ln_rows8(t, s, g2, be2, smu, srs);
    __syncthreads();
#pragma unroll
    for (int gg = 0; gg < 8; gg++)
        vn[(size_t)(g0 + gg) * D + d] = s[gg][d];
}

// ---------------- h2 += vn[batch] ----------------
__global__ void add_vn_kernel(float* __restrict__ h2, const int* __restrict__ batch,
                              const float* __restrict__ vn)
{
    int n = blockIdx.x, d = threadIdx.x;
    __shared__ int bg;
    if (d == 0) bg = batch[n];
    __syncthreads();
    h2[(size_t)n * D + d] += vn[(size_t)bg * D + d];
}

// ---------------- launcher ----------------
extern "C" void kernel_launch(void* const* d_in, const int* in_sizes, int n_in,
                              void* d_out, int out_size)
{
    const int*   x          = (const int*)  d_in[0];
    const int*   edge_attr  = (const int*)  d_in[1];
    const int*   edge_index = (const int*)  d_in[2];
    const int*   batch      = (const int*)  d_in[3];
    const float* atom_emb   = (const float*)d_in[4];
    const float* bond_emb   = (const float*)d_in[5];
    const float* vn_emb     = (const float*)d_in[6];
    const float* gcn_w      = (const float*)d_in[7];
    const float* gcn_b      = (const float*)d_in[8];
    const float* norm_g     = (const float*)d_in[9];
    const float* norm_b     = (const float*)d_in[10];
    const float* ffn_w      = (const float*)d_in[11];
    const float* ffn_b      = (const float*)d_in[12];
    const float* vn_w1      = (const float*)d_in[13];
    const float* vn_b1      = (const float*)d_in[14];
    const float* vn_g1      = (const float*)d_in[15];
    const float* vn_be1     = (const float*)d_in[16];
    const float* vn_w2      = (const float*)d_in[17];
    const float* vn_b2      = (const float*)d_in[18];
    const float* vn_g2      = (const float*)d_in[19];
    const float* vn_be2     = (const float*)d_in[20];

    float* out       = (float*)d_out;                       // h_graph [N,256]
    float* out_hinit = out + (size_t)N_NODES * D;           // h_init  [N,256]

    float *ph, *ph2, *pagg, *pvn; int* poff;
    cudaGetSymbolAddress((void**)&ph,   g_h);
    cudaGetSymbolAddress((void**)&ph2,  g_h2);
    cudaGetSymbolAddress((void**)&pagg, g_agg);
    cudaGetSymbolAddress((void**)&pvn,  g_vn);
    cudaGetSymbolAddress((void**)&poff, g_off);

    const int GEMM_GRID = (N_NODES + 63) / 64;   // 1563
    const int EDGE_GRID = (N_EDGES + 3) / 4;     // 75000

    node_init_kernel<<<N_NODES, 256>>>(x, atom_emb, vn_emb, ph, pagg, pvn, out_hinit);
    offsets_kernel<<<(NGRAPHS + 1 + 255) / 256, 256>>>(batch, poff);

    // ----- layer 0 -----
    edge_msg_kernel<<<EDGE_GRID, 256>>>((const float4*)ph, edge_index, edge_attr,
                                        (const float4*)bond_emb, pagg);
    gemm_kernel<256><<<GEMM_GRID, 256>>>(ph, pagg, gcn_w, gcn_b, nullptr, ph, N_NODES, D);
    gemm_kernel<64><<<GEMM_GRID, 256>>>(ph, nullptr, ffn_w, ffn_b, nullptr, out, N_NODES, D);

    // ----- layers 1..3 (layers 4..6 are dead code: only out[0..3] reach h_graph) -----
    for (int l = 1; l < 4; l++) {
        int j = l - 1;
        ln_relu_kernel<<<N_NODES, 256>>>(ph, norm_g + (size_t)j * D, norm_b + (size_t)j * D, ph2, pagg);
        vn_mlp_kernel<<<NGRAPHS / 8, 256>>>(ph2, poff,
                                            vn_w1 + (size_t)j * D * D, vn_b1 + (size_t)j * D,
                                            vn_g1 + (size_t)j * D,     vn_be1 + (size_t)j * D,
                                            vn_w2 + (size_t)j * D * D, vn_b2 + (size_t)j * D,
                                            vn_g2 + (size_t)j * D,     vn_be2 + (size_t)j * D,
                                            pvn);
        add_vn_kernel<<<N_NODES, 256>>>(ph2, batch, pvn);
        edge_msg_kernel<<<EDGE_GRID, 256>>>((const float4*)ph2, edge_index, edge_attr,
                                            (const float4*)bond_emb, pagg);
        gemm_kernel<256><<<GEMM_GRID, 256>>>(ph2, pagg, gcn_w + (size_t)l * D * D,
                                             gcn_b + (size_t)l * D, ph, ph, N_NODES, D);
        gemm_kernel<64><<<GEMM_GRID, 256>>>(ph, nullptr, ffn_w + (size_t)l * D * 64,
                                            ffn_b + (size_t)l * 64, nullptr,
                                            out + (size_t)l * 64, N_NODES, D);
    }
}

// round 2
// speedup vs baseline: 1.0020x; 1.0020x over previous
#include <cuda_runtime.h>
#include <stddef.h>

#define N_NODES 100000
#define N_EDGES 300000
#define NGRAPHS 3000
#define D 256
#define MSG_EPS 1e-7f
#define LN_EPS  1e-5f

// ---------------- scratch (static device allocations; no cudaMalloc) ----------------
__device__ __align__(16) float g_h  [(size_t)N_NODES * D];
__device__ __align__(16) float g_h2 [(size_t)N_NODES * D];
__device__ __align__(16) float g_agg[(size_t)N_NODES * D];
__device__ __align__(16) float g_vn [(size_t)NGRAPHS * D];
__device__ int g_off[NGRAPHS + 1];

// ---------------- node init: atom embedding sum, h_init out, h = h0 + vn_emb ----------------
__global__ void node_init_kernel(const int* __restrict__ x,
                                 const float* __restrict__ atom_emb,
                                 const float* __restrict__ vn_emb,
                                 float* __restrict__ h,
                                 float* __restrict__ agg,
                                 float* __restrict__ vn,
                                 float* __restrict__ out_hinit)
{
    int n = blockIdx.x;
    int d = threadIdx.x;
    __shared__ int xi[9];
    if (d < 9) xi[d] = x[n * 9 + d];
    __syncthreads();
    float s = 0.f;
#pragma unroll
    for (int f = 0; f < 9; f++)
        s += atom_emb[((size_t)f * 64 + xi[f]) * D + d];
    size_t idx = (size_t)n * D + d;
    out_hinit[idx] = s;
    h[idx] = s + vn_emb[d];
    agg[idx] = 0.f;
    if (n < NGRAPHS) vn[(size_t)n * D + d] = vn_emb[d];
}

// ---------------- graph segment offsets via binary search (batch is sorted) ----------------
__global__ void offsets_kernel(const int* __restrict__ batch, int* __restrict__ off)
{
    int g = blockIdx.x * blockDim.x + threadIdx.x;
    if (g > NGRAPHS) return;
    int lo = 0, hi = N_NODES;
    while (lo < hi) {
        int mid = (lo + hi) >> 1;
        if (batch[mid] < g) lo = mid + 1; else hi = mid;
    }
    off[g] = lo;
}

// ---------------- edge messages: msg = relu(h[src]+edge_emb)+eps, scatter-add to agg[dst] ----------------
__global__ void edge_msg_kernel(const float4* __restrict__ hin,
                                const int* __restrict__ ei,
                                const int* __restrict__ ea,
                                const float4* __restrict__ bond,   // [3][8][64] float4
                                float* __restrict__ agg)
{
    int e = blockIdx.x * 4 + (threadIdx.x >> 6);
    if (e >= N_EDGES) return;
    int q = threadIdx.x & 63;
    int src = __ldg(&ei[e]);
    int dst = __ldg(&ei[N_EDGES + e]);
    int a0 = __ldg(&ea[3 * e + 0]);
    int a1 = __ldg(&ea[3 * e + 1]);
    int a2 = __ldg(&ea[3 * e + 2]);
    float4 v  = hin[(size_t)src * 64 + q];
    float4 b0 = bond[(size_t)(0 * 8 + a0) * 64 + q];
    float4 b1 = bond[(size_t)(1 * 8 + a1) * 64 + q];
    float4 b2 = bond[(size_t)(2 * 8 + a2) * 64 + q];
    float mx = fmaxf(v.x + b0.x + b1.x + b2.x, 0.f) + MSG_EPS;
    float my = fmaxf(v.y + b0.y + b1.y + b2.y, 0.f) + MSG_EPS;
    float mz = fmaxf(v.z + b0.z + b1.z + b2.z, 0.f) + MSG_EPS;
    float mw = fmaxf(v.w + b0.w + b1.w + b2.w, 0.f) + MSG_EPS;
    float* base = &agg[(size_t)dst * D + q * 4];
    atomicAdd(base + 0, mx);
    atomicAdd(base + 1, my);
    atomicAdd(base + 2, mz);
    atomicAdd(base + 3, mw);
}

// ---------------- generic GEMM: out = (A1 [+A2]) @ W + bias [+ res] ----------------
// A: [M, 256] fp32 row-major. W: [256, BN] row-major. out row stride ldout.
template<int BN>
__global__ __launch_bounds__(256)
void gemm_kernel(const float* __restrict__ A1, const float* __restrict__ A2,
                 const float* __restrict__ W, const float* __restrict__ bias,
                 const float* __restrict__ res, float* __restrict__ out,
                 int M, int ldout)
{
    constexpr int BM = 64, BK = 32, K = D;
    constexpr int NG = BN / 64;
    __shared__ float As[BK][BM];
    __shared__ float Bs[BK][BN];
    const int tid = threadIdx.x;
    const int tx = tid & 15;        // 16 col-groups
    const int ty = tid >> 4;        // 16 row-groups
    const int m0 = blockIdx.x * BM;

    float acc[4][NG * 4];
#pragma unroll
    for (int i = 0; i < 4; i++)
#pragma unroll
        for (int j = 0; j < NG * 4; j++) acc[i][j] = 0.f;

    for (int k0 = 0; k0 < K; k0 += BK) {
        // --- load A tile (64 x 32), transposed into As[k][m], zero-padded past M ---
        {
            int r  = tid >> 3;            // 0..31
            int kc = (tid & 7) * 4;       // 0..28
#pragma unroll
            for (int it = 0; it < 2; it++) {
                int row = r + it * 32;
                int m = m0 + row;
                float4 v = make_float4(0.f, 0.f, 0.f, 0.f);
                if (m < M) {
                    v = *reinterpret_cast<const float4*>(&A1[(size_t)m * K + k0 + kc]);
                    if (A2) {
                        float4 w = *reinterpret_cast<const float4*>(&A2[(size_t)m * K + k0 + kc]);
                        v.x += w.x; v.y += w.y; v.z += w.z; v.w += w.w;
                    }
                }
                As[kc + 0][row] = v.x;
                As[kc + 1][row] = v.y;
                As[kc + 2][row] = v.z;
                As[kc + 3][row] = v.w;
            }
        }
        // --- load B tile (32 x BN) ---
        {
            constexpr int PASS = (BK * BN) / 1024;
            constexpr int RP   = 1024 / BN;
            int c4 = (tid % (BN / 4)) * 4;
            int rr = tid / (BN / 4);
#pragma unroll
            for (int it = 0; it < PASS; it++) {
                int kk = rr + it * RP;
                float4 v = *reinterpret_cast<const float4*>(&W[(size_t)(k0 + kk) * BN + c4]);
                *reinterpret_cast<float4*>(&Bs[kk][c4]) = v;
            }
        }
        __syncthreads();
#pragma unroll
        for (int k = 0; k < BK; k++) {
            float4 a4 = *reinterpret_cast<const float4*>(&As[k][ty * 4]);
            float av[4] = {a4.x, a4.y, a4.z, a4.w};
#pragma unroll
            for (int g = 0; g < NG; g++) {
                float4 b4 = *reinterpret_cast<const float4*>(&Bs[k][g * 64 + tx * 4]);
                float bv[4] = {b4.x, b4.y, b4.z, b4.w};
#pragma unroll
                for (int i = 0; i < 4; i++)
#pragma unroll
                    for (int j = 0; j < 4; j++)
                        acc[i][g * 4 + j] = fmaf(av[i], bv[j], acc[i][g * 4 + j]);
            }
        }
        __syncthreads();
    }
    // --- epilogue ---
#pragma unroll
    for (int i = 0; i < 4; i++) {
        int m = m0 + ty * 4 + i;
        if (m >= M) continue;
#pragma unroll
        for (int g = 0; g < NG; g++) {
            int c = g * 64 + tx * 4;
            float4 v;
            v.x = acc[i][g * 4 + 0] + bias[c + 0];
            v.y = acc[i][g * 4 + 1] + bias[c + 1];
            v.z = acc[i][g * 4 + 2] + bias[c + 2];
            v.w = acc[i][g * 4 + 3] + bias[c + 3];
            if (res) {
                float4 r4 = *reinterpret_cast<const float4*>(&res[(size_t)m * D + c]);
                v.x += r4.x; v.y += r4.y; v.z += r4.z; v.w += r4.w;
            }
            *reinterpret_cast<float4*>(&out[(size_t)m * ldout + c]) = v;
        }
    }
}

// ---------------- LayerNorm + ReLU per node (also zeroes agg for next conv) ----------------
__global__ void ln_relu_kernel(const float* __restrict__ h,
                               const float* __restrict__ gam,
                               const float* __restrict__ bet,
                               float* __restrict__ h2,
                               float* __restrict__ agg)
{
    int n = blockIdx.x, d = threadIdx.x;
    size_t idx = (size_t)n * D + d;
    float v = h[idx];
    float a = v, b = v * v;
    __shared__ float sa[8], sb[8];
    int lane = d & 31, w = d >> 5;
#pragma unroll
    for (int o = 16; o; o >>= 1) {
        a += __shfl_down_sync(0xffffffffu, a, o);
        b += __shfl_down_sync(0xffffffffu, b, o);
    }
    if (lane == 0) { sa[w] = a; sb[w] = b; }
    __syncthreads();
    if (w == 0) {
        a = (lane < 8) ? sa[lane] : 0.f;
        b = (lane < 8) ? sb[lane] : 0.f;
#pragma unroll
        for (int o = 4; o; o >>= 1) {
            a += __shfl_down_sync(0xffffffffu, a, o);
            b += __shfl_down_sync(0xffffffffu, b, o);
        }
        if (lane == 0) { sa[0] = a; sb[0] = b; }
    }
    __syncthreads();
    float mu  = sa[0] * (1.f / D);
    float var = sb[0] * (1.f / D) - mu * mu;
    float y = (v - mu) * rsqrtf(var + LN_EPS) * gam[d] + bet[d];
    h2[idx]  = fmaxf(y, 0.f);
    agg[idx] = 0.f;
}

// ---------------- virtual-node path: vn = MLP(segment_sum(h2) + vn), 8 graphs/block ----------------
__device__ __forceinline__ void ln_rows8(float (*t)[D], float (*s)[D],
                                         const float* __restrict__ gam,
                                         const float* __restrict__ bet,
                                         float* smu, float* srs)
{
    int lane = threadIdx.x & 31, w = threadIdx.x >> 5;   // warp w handles graph w
    float a = 0.f, b = 0.f;
#pragma unroll
    for (int i = 0; i < 8; i++) {
        float v = t[w][lane + 32 * i];
        a += v; b += v * v;
    }
#pragma unroll
    for (int o = 16; o; o >>= 1) {
        a += __shfl_down_sync(0xffffffffu, a, o);
        b += __shfl_down_sync(0xffffffffu, b, o);
    }
    if (lane == 0) {
        float mu = a * (1.f / D);
        float var = b * (1.f / D) - mu * mu;
        smu[w] = mu;
        srs[w] = rsqrtf(var + LN_EPS);
    }
    __syncthreads();
    int d = threadIdx.x;
    float gd = gam[d], bd = bet[d];
#pragma unroll
    for (int gg = 0; gg < 8; gg++) {
        float v = (t[gg][d] - smu[gg]) * srs[gg] * gd + bd;
        s[gg][d] = fmaxf(v, 0.f);
    }
}

__global__ void vn_mlp_kernel(const float* __restrict__ h2, const int* __restrict__ off,
                              const float* __restrict__ W1, const float* __restrict__ b1,
                              const float* __restrict__ g1, const float* __restrict__ be1,
                              const float* __restrict__ W2, const float* __restrict__ b2,
                              const float* __restrict__ g2, const float* __restrict__ be2,
                              float* __restrict__ vn)
{
    __shared__ float s[8][D];
    __shared__ float t[8][D];
    __shared__ float smu[8], srs[8];
    int d = threadIdx.x;
    int g0 = blockIdx.x * 8;

    // segment sum + current vn
#pragma unroll
    for (int gg = 0; gg < 8; gg++) {
        int g = g0 + gg;
        float acc = vn[(size_t)g * D + d];
        int n1 = off[g + 1];
        for (int n = off[g]; n < n1; n++)
            acc += h2[(size_t)n * D + d];
        s[gg][d] = acc;
    }
    __syncthreads();

    // linear 1
    float y[8];
#pragma unroll
    for (int gg = 0; gg < 8; gg++) y[gg] = b1[d];
    for (int k = 0; k < D; k++) {
        float w = W1[(size_t)k * D + d];
#pragma unroll
        for (int gg = 0; gg < 8; gg++) y[gg] = fmaf(s[gg][k], w, y[gg]);
    }
    __syncthreads();
#pragma unroll
    for (int gg = 0; gg < 8; gg++) t[gg][d] = y[gg];
    __syncthreads();
    ln_rows8(t, s, g1, be1, smu, srs);   // s = relu(LN(t))
    __syncthreads();

    // linear 2
#pragma unroll
    for (int gg = 0; gg < 8; gg++) y[gg] = b2[d];
    for (int k = 0; k < D; k++) {
        float w = W2[(size_t)k * D + d];
#pragma unroll
        for (int gg = 0; gg < 8; gg++) y[gg] = fmaf(s[gg][k], w, y[gg]);
    }
    __syncthreads();
#pragma unroll
    for (int gg = 0; gg < 8; gg++) t[gg][d] = y[gg];
    __syncthreads();
    ln_rows8(t, s, g2, be2, smu, srs);
    __syncthreads();
#pragma unroll
    for (int gg = 0; gg < 8; gg++)
        vn[(size_t)(g0 + gg) * D + d] = s[gg][d];
}

// ---------------- h2 += vn[batch] ----------------
__global__ void add_vn_kernel(float* __restrict__ h2, const int* __restrict__ batch,
                              const float* __restrict__ vn)
{
    int n = blockIdx.x, d = threadIdx.x;
    __shared__ int bg;
    if (d == 0) bg = batch[n];
    __syncthreads();
    h2[(size_t)n * D + d] += vn[(size_t)bg * D + d];
}

// ---------------- launcher ----------------
extern "C" void kernel_launch(void* const* d_in, const int* in_sizes, int n_in,
                              void* d_out, int out_size)
{
    const int*   x          = (const int*)  d_in[0];
    const int*   edge_attr  = (const int*)  d_in[1];
    const int*   edge_index = (const int*)  d_in[2];
    const int*   batch      = (const int*)  d_in[3];
    const float* atom_emb   = (const float*)d_in[4];
    const float* bond_emb   = (const float*)d_in[5];
    const float* vn_emb     = (const float*)d_in[6];
    const float* gcn_w      = (const float*)d_in[7];
    const float* gcn_b      = (const float*)d_in[8];
    const float* norm_g     = (const float*)d_in[9];
    const float* norm_b     = (const float*)d_in[10];
    const float* ffn_w      = (const float*)d_in[11];
    const float* ffn_b      = (const float*)d_in[12];
    const float* vn_w1      = (const float*)d_in[13];
    const float* vn_b1      = (const float*)d_in[14];
    const float* vn_g1      = (const float*)d_in[15];
    const float* vn_be1     = (const float*)d_in[16];
    const float* vn_w2      = (const float*)d_in[17];
    const float* vn_b2      = (const float*)d_in[18];
    const float* vn_g2      = (const float*)d_in[19];
    const float* vn_be2     = (const float*)d_in[20];

    float* out       = (float*)d_out;                       // h_graph [N,256]
    float* out_hinit = out + (size_t)N_NODES * D;           // h_init  [N,256]

    float *ph, *ph2, *pagg, *pvn; int* poff;
    cudaGetSymbolAddress((void**)&ph,   g_h);
    cudaGetSymbolAddress((void**)&ph2,  g_h2);
    cudaGetSymbolAddress((void**)&pagg, g_agg);
    cudaGetSymbolAddress((void**)&pvn,  g_vn);
    cudaGetSymbolAddress((void**)&poff, g_off);

    const int GEMM_GRID = (N_NODES + 63) / 64;   // 1563
    const int EDGE_GRID = (N_EDGES + 3) / 4;     // 75000

    node_init_kernel<<<N_NODES, 256>>>(x, atom_emb, vn_emb, ph, pagg, pvn, out_hinit);
    offsets_kernel<<<(NGRAPHS + 1 + 255) / 256, 256>>>(batch, poff);

    // ----- layer 0 -----
    edge_msg_kernel<<<EDGE_GRID, 256>>>((const float4*)ph, edge_index, edge_attr,
                                        (const float4*)bond_emb, pagg);
    gemm_kernel<256><<<GEMM_GRID, 256>>>(ph, pagg, gcn_w, gcn_b, nullptr, ph, N_NODES, D);
    gemm_kernel<64><<<GEMM_GRID, 256>>>(ph, nullptr, ffn_w, ffn_b, nullptr, out, N_NODES, D);

    // ----- layers 1..3 (layers 4..6 are dead code: only out[0..3] reach h_graph) -----
    for (int l = 1; l < 4; l++) {
        int j = l - 1;
        ln_relu_kernel<<<N_NODES, 256>>>(ph, norm_g + (size_t)j * D, norm_b + (size_t)j * D, ph2, pagg);
        vn_mlp_kernel<<<NGRAPHS / 8, 256>>>(ph2, poff,
                                            vn_w1 + (size_t)j * D * D, vn_b1 + (size_t)j * D,
                                            vn_g1 + (size_t)j * D,     vn_be1 + (size_t)j * D,
                                            vn_w2 + (size_t)j * D * D, vn_b2 + (size_t)j * D,
                                            vn_g2 + (size_t)j * D,     vn_be2 + (size_t)j * D,
                                            pvn);
        add_vn_kernel<<<N_NODES, 256>>>(ph2, batch, pvn);
        edge_msg_kernel<<<EDGE_GRID, 256>>>((const float4*)ph2, edge_index, edge_attr,
                                            (const float4*)bond_emb, pagg);
        gemm_kernel<256><<<GEMM_GRID, 256>>>(ph2, pagg, gcn_w + (size_t)l * D * D,
                                             gcn_b + (size_t)l * D, ph, ph, N_NODES, D);
        gemm_kernel<64><<<GEMM_GRID, 256>>>(ph, nullptr, ffn_w + (size_t)l * D * 64,
                                            ffn_b + (size_t)l * 64, nullptr,
                                            out + (size_t)l * 64, N_NODES, D);
    }
}